// round 12
// baseline (speedup 1.0000x reference)
#include <cuda_runtime.h>
#include <cuda_fp16.h>
#include <math.h>

#define Tt 4096
#define Dd 1024
#define Hh 4096
#define Ee 8
#define Kk 2

// ---------------- device scratch ----------------
__device__ int    g_cnt[Ee];
__device__ int    g_slot[Ee * Tt];
__device__ float  g_wt[Tt * Kk];
__device__ float  g_probs[Tt * Ee];
__device__ __half g_xh[(size_t)Tt * Dd];          // x in fp16
__device__ __half g_w1h[(size_t)Ee * Dd * Hh];    // w1 in fp16
__device__ __half g_w2h[(size_t)Ee * Hh * Dd];    // w2 in fp16
__device__ __half g_h[(size_t)Tt * Kk * Hh];      // gelu(x@w1+b1) per slot (fp16)
__device__ float  g_y[(size_t)Tt * Kk * Dd];      // (h@w2+b2) per slot (fp32)

// ---------------- helpers ----------------
__device__ __forceinline__ unsigned smem_u32(const void* p) {
    unsigned a;
    asm("{ .reg .u64 t; cvta.to.shared.u64 t, %1; cvt.u32.u64 %0, t; }"
        : "=r"(a) : "l"(p));
    return a;
}
__device__ __forceinline__ void cp16(unsigned saddr, const void* g) {
    asm volatile("cp.async.cg.shared.global [%0], [%1], 16;"
                 :: "r"(saddr), "l"(g) : "memory");
}
__device__ __forceinline__ void mma_f16(float* d, const unsigned* a, const unsigned* b) {
    asm volatile(
        "mma.sync.aligned.m16n8k16.row.col.f32.f16.f16.f32 "
        "{%0,%1,%2,%3}, {%4,%5,%6,%7}, {%8,%9}, {%0,%1,%2,%3};"
        : "+f"(d[0]), "+f"(d[1]), "+f"(d[2]), "+f"(d[3])
        : "r"(a[0]), "r"(a[1]), "r"(a[2]), "r"(a[3]), "r"(b[0]), "r"(b[1]));
}
#define LDSM_X4(r, addr) \
    asm volatile("ldmatrix.sync.aligned.m8n8.x4.shared.b16 {%0,%1,%2,%3}, [%4];" \
        : "=r"((r)[0]), "=r"((r)[1]), "=r"((r)[2]), "=r"((r)[3]) : "r"(addr))
#define LDSM_X4_T(r, addr) \
    asm volatile("ldmatrix.sync.aligned.m8n8.x4.trans.shared.b16 {%0,%1,%2,%3}, [%4];" \
        : "=r"((r)[0]), "=r"((r)[1]), "=r"((r)[2]), "=r"((r)[3]) : "r"(addr))

// ---------------- zero counters ----------------
__global__ void zero_kernel() {
    int i = threadIdx.x;
    if (i < Ee) g_cnt[i] = 0;
}

// ---------------- f32 -> f16 convert (8 elems/thread) ----------------
__global__ void f2h_kernel(const float* __restrict__ s, int which, int n) {
    __half* d = (which == 0) ? g_xh : (which == 1) ? g_w1h : g_w2h;
    size_t i = ((size_t)blockIdx.x * blockDim.x + threadIdx.x) * 8;
    if (i >= (size_t)n) return;
    float4 v0 = *(const float4*)(s + i);
    float4 v1 = *(const float4*)(s + i + 4);
    __half2 h0 = __floats2half2_rn(v0.x, v0.y);
    __half2 h1 = __floats2half2_rn(v0.z, v0.w);
    __half2 h2 = __floats2half2_rn(v1.x, v1.y);
    __half2 h3 = __floats2half2_rn(v1.z, v1.w);
    uint4 o;
    o.x = *(unsigned*)&h0; o.y = *(unsigned*)&h1;
    o.z = *(unsigned*)&h2; o.w = *(unsigned*)&h3;
    *(uint4*)(d + i) = o;
}

// ---------------- router: 1 warp per token ----------------
__global__ void router_kernel(const float* __restrict__ x,
                              const float* __restrict__ rw) {
    int tid = threadIdx.x;
    int warp = tid >> 5, lane = tid & 31;
    int t = blockIdx.x * 8 + warp;

    const float* xr = x + (size_t)t * Dd;
    float acc[Ee];
#pragma unroll
    for (int e = 0; e < Ee; e++) acc[e] = 0.f;
    for (int d = lane; d < Dd; d += 32) {
        float xv = xr[d];
#pragma unroll
        for (int e = 0; e < Ee; e++) acc[e] += xv * rw[e * Dd + d];
    }
#pragma unroll
    for (int e = 0; e < Ee; e++)
#pragma unroll
        for (int off = 16; off > 0; off >>= 1)
            acc[e] += __shfl_xor_sync(0xffffffffu, acc[e], off);

    if (lane == 0) {
        float mx = acc[0];
#pragma unroll
        for (int e = 1; e < Ee; e++) mx = fmaxf(mx, acc[e]);
        float pe[Ee], s = 0.f;
#pragma unroll
        for (int e = 0; e < Ee; e++) { pe[e] = __expf(acc[e] - mx); s += pe[e]; }
        float inv = 1.f / s;
#pragma unroll
        for (int e = 0; e < Ee; e++) { pe[e] *= inv; g_probs[t * Ee + e] = pe[e]; }
        int i1 = 0;
#pragma unroll
        for (int e = 1; e < Ee; e++) if (pe[e] > pe[i1]) i1 = e;
        int i2 = (i1 == 0) ? 1 : 0;
#pragma unroll
        for (int e = 0; e < Ee; e++) if (e != i1 && pe[e] > pe[i2]) i2 = e;
        float denom = pe[i1] + pe[i2] + 1e-8f;
        int p1 = atomicAdd(&g_cnt[i1], 1);
        g_slot[i1 * Tt + p1] = t * 2 + 0;
        g_wt[t * 2 + 0] = pe[i1] / denom;
        int p2 = atomicAdd(&g_cnt[i2], 1);
        g_slot[i2 * Tt + p2] = t * 2 + 1;
        g_wt[t * 2 + 1] = pe[i2] / denom;
    }
}

// ---------------- fp16 mma.sync grouped GEMM ----------------
// CTA tile 128x128, K-chunk 64, 8 warps (2x4), warp tile 64x32, 2 CTAs/SM.
// 3-stage cp.async ring, ONE __syncthreads per chunk.
// NEW: explicit fragment double-buffering across k-steps (hide ldmatrix latency).
#define BK 64
#define A_BUF_B (128 * 144)                   // 18432 B
#define B_BUF_B (64 * 272)                    // 17408 B
#define STAGE_B (A_BUF_B + B_BUF_B)           // 35840 B
#define SM_SLOT_B (3 * STAGE_B)               // 107520
#define SMEM_BYTES (SM_SLOT_B + 512)          // 108032

template<int LDA, int LDW, int KTOT, int NTOT, int SHIFT, bool GELU, int LDO>
__global__ __launch_bounds__(256, 2)
void mma_gemm(const float* __restrict__ bias) {
    const int e = blockIdx.z;
    const int ne = g_cnt[e];
    const int row0 = blockIdx.x * 128;
    if (row0 >= ne) return;
    const int n0 = blockIdx.y * 128;

    extern __shared__ __align__(16) char smem[];
    int* slot_s = (int*)(smem + SM_SLOT_B);
    const unsigned sb = smem_u32(smem);

    const int tid = threadIdx.x, wid = tid >> 5, lane = tid & 31;
    const int g = lane >> 2, c = lane & 3;

    const __half* A = SHIFT ? g_xh : g_h;
    const __half* W = GELU ? g_w1h : g_w2h;

    if (tid < 128) {
        int r = row0 + tid;
        slot_s[tid] = g_slot[e * Tt + ((r < ne) ? r : (ne - 1))];
    }
    __syncthreads();

    // cp.async mappings: A 2 thr/row (4x16B), B 4 thr/row (4x16B)
    const int arow = tid >> 1, acb = (tid & 1) * 4;
    const __half* aSrc = A + (size_t)(slot_s[arow] >> SHIFT) * LDA + acb * 8;
    const unsigned aOff = arow * 144 + acb * 16;
    const int brow = tid >> 2, bcb = (tid & 3) * 4;
    const __half* bSrc = W + (size_t)e * KTOT * LDW + (size_t)brow * LDW + n0 + bcb * 8;
    const unsigned bOff = A_BUF_B + brow * 272 + bcb * 16;

    const int NK = KTOT / BK;

    // prologue: chunks 0,1 into stages 0,1
#pragma unroll
    for (int p = 0; p < 2; p++) {
        const unsigned s0 = sb + p * STAGE_B;
        const __half* ap = aSrc + (size_t)p * BK;
        const __half* bp = bSrc + (size_t)p * BK * LDW;
#pragma unroll
        for (int q = 0; q < 4; q++) cp16(s0 + aOff + q * 16, ap + q * 8);
#pragma unroll
        for (int q = 0; q < 4; q++) cp16(s0 + bOff + q * 16, bp + q * 8);
        asm volatile("cp.async.commit_group;" ::: "memory");
    }

    const int wm = (wid >> 2) * 64;
    const int wn = (wid & 3) * 32;

    // ldmatrix lane base offsets (within a stage)
    const unsigned aLd = (wm + (lane & 15)) * 144 + (lane >> 4) * 16;
    const unsigned bLd = A_BUF_B + (lane & 15) * 272 + wn * 2 + (lane >> 4) * 16;

    float acc[4][4][4];
#pragma unroll
    for (int mf = 0; mf < 4; mf++)
#pragma unroll
        for (int nf = 0; nf < 4; nf++)
#pragma unroll
            for (int v = 0; v < 4; v++) acc[mf][nf][v] = 0.f;

    // ping-pong fragment sets
    unsigned afr[2][4][4], bfr[2][2][4];

    int cs = 0;  // compute stage
    for (int i = 0; i < NK; i++) {
        if (i + 1 < NK) asm volatile("cp.async.wait_group 1;" ::: "memory");
        else            asm volatile("cp.async.wait_group 0;" ::: "memory");
        __syncthreads();

        // issue chunk i+2 into stage (cs+2)%3 — freed: all warps passed compute(i-1)
        if (i + 2 < NK) {
            const int ts = (cs == 0) ? 2 : cs - 1;
            const unsigned s0 = sb + ts * STAGE_B;
            const __half* ap = aSrc + (size_t)(i + 2) * BK;
            const __half* bp = bSrc + (size_t)(i + 2) * BK * LDW;
#pragma unroll
            for (int q = 0; q < 4; q++) cp16(s0 + aOff + q * 16, ap + q * 8);
#pragma unroll
            for (int q = 0; q < 4; q++) cp16(s0 + bOff + q * 16, bp + q * 8);
            asm volatile("cp.async.commit_group;" ::: "memory");
        }

        const unsigned ab = sb + cs * STAGE_B + aLd;
        const unsigned bb0 = sb + cs * STAGE_B + bLd;

        // software-pipelined k-steps: load ks+1 frags while computing ks
#pragma unroll
        for (int mf = 0; mf < 4; mf++)
            LDSM_X4(afr[0][mf], ab + mf * (16 * 144));
        LDSM_X4_T(bfr[0][0], bb0);
        LDSM_X4_T(bfr[0][1], bb0 + 32);

#pragma unroll
        for (int ks = 0; ks < 4; ks++) {
            const int cur = ks & 1, nxt = cur ^ 1;
            if (ks < 3) {
#pragma unroll
                for (int mf = 0; mf < 4; mf++)
                    LDSM_X4(afr[nxt][mf], ab + mf * (16 * 144) + (ks + 1) * 32);
                LDSM_X4_T(bfr[nxt][0], bb0 + (ks + 1) * (16 * 272));
                LDSM_X4_T(bfr[nxt][1], bb0 + (ks + 1) * (16 * 272) + 32);
            }
#pragma unroll
            for (int mf = 0; mf < 4; mf++)
#pragma unroll
                for (int nf = 0; nf < 4; nf++)
                    mma_f16(acc[mf][nf], afr[cur][mf], &bfr[cur][nf >> 1][(nf & 1) * 2]);
        }
        cs = (cs == 2) ? 0 : cs + 1;
    }

    // ---------------- epilogue ----------------
#pragma unroll
    for (int mf = 0; mf < 4; mf++) {
#pragma unroll
        for (int half_i = 0; half_i < 2; half_i++) {
            const int r = wm + mf * 16 + g + half_i * 8;
            if (row0 + r >= ne) continue;
            const int s = slot_s[r];
#pragma unroll
            for (int nf = 0; nf < 4; nf++) {
                const int col = wn + nf * 8 + c * 2;
                float v0 = acc[mf][nf][half_i * 2 + 0] + bias[e * NTOT + n0 + col];
                float v1 = acc[mf][nf][half_i * 2 + 1] + bias[e * NTOT + n0 + col + 1];
                if (GELU) {
                    v0 = 0.5f * v0 * (1.f + erff(v0 * 0.70710678118654752440f));
                    v1 = 0.5f * v1 * (1.f + erff(v1 * 0.70710678118654752440f));
                    __half2 h2 = __floats2half2_rn(v0, v1);
                    *(__half2*)(g_h + (size_t)s * LDO + n0 + col) = h2;
                } else {
                    float2 o; o.x = v0; o.y = v1;
                    *(float2*)(g_y + (size_t)s * LDO + n0 + col) = o;
                }
            }
        }
    }
}

// ---------------- combine ----------------
__global__ void combine_kernel(float* __restrict__ out) {
    int i = blockIdx.x * blockDim.x + threadIdx.x;
    int t = i >> 8;
    int d4 = i & 255;
    float w0 = g_wt[2 * t], w1 = g_wt[2 * t + 1];
    const float4* y = (const float4*)g_y;
    float4 a = y[(size_t)(2 * t) * 256 + d4];
    float4 b = y[(size_t)(2 * t + 1) * 256 + d4];
    float4 o;
    o.x = w0 * a.x + w1 * b.x;
    o.y = w0 * a.y + w1 * b.y;
    o.z = w0 * a.z + w1 * b.z;
    o.w = w0 * a.w + w1 * b.w;
    ((float4*)out)[i] = o;
}

// ---------------- load-balancing loss ----------------
__global__ void loss_kernel(float* __restrict__ out, int write_loss) {
    __shared__ float sred[256 * Ee];
    int tid = threadIdx.x;
    float l[Ee];
#pragma unroll
    for (int e = 0; e < Ee; e++) l[e] = 0.f;
    for (int t = tid; t < Tt; t += 256)
#pragma unroll
        for (int e = 0; e < Ee; e++) l[e] += g_probs[t * Ee + e];
#pragma unroll
    for (int e = 0; e < Ee; e++) sred[tid * Ee + e] = l[e];
    __syncthreads();
    for (int s = 128; s > 0; s >>= 1) {
        if (tid < s)
#pragma unroll
            for (int e = 0; e < Ee; e++)
                sred[tid * Ee + e] += sred[(tid + s) * Ee + e];
        __syncthreads();
    }
    if (tid == 0 && write_loss) {
        float loss = 0.f;
        for (int e = 0; e < Ee; e++) {
            float mean_p = sred[e] / (float)Tt;
            float frac = (float)g_cnt[e] / (float)(Tt * Kk);
            loss += mean_p * frac;
        }
        out[(size_t)Tt * Dd] = loss * (float)Ee;
    }
}

// ---------------- launch ----------------
extern "C" void kernel_launch(void* const* d_in, const int* in_sizes, int n_in,
                              void* d_out, int out_size) {
    const float* x  = (const float*)d_in[0];
    const float* rw = (const float*)d_in[1];
    const float* w1 = (const float*)d_in[2];
    const float* b1 = (const float*)d_in[3];
    const float* w2 = (const float*)d_in[4];
    const float* b2 = (const float*)d_in[5];
    float* out = (float*)d_out;

    cudaFuncSetAttribute(mma_gemm<Dd, Hh, Dd, Hh, 1, true, Hh>,
                         cudaFuncAttributeMaxDynamicSharedMemorySize, SMEM_BYTES);
    cudaFuncSetAttribute(mma_gemm<Hh, Dd, Hh, Dd, 0, false, Dd>,
                         cudaFuncAttributeMaxDynamicSharedMemorySize, SMEM_BYTES);

    zero_kernel<<<1, 32>>>();
    router_kernel<<<Tt / 8, 256>>>(x, rw);

    // f32 -> f16 conversions
    f2h_kernel<<<(Tt * Dd / 8 + 255) / 256, 256>>>(x, 0, Tt * Dd);
    f2h_kernel<<<(Ee * Dd * Hh / 8 + 255) / 256, 256>>>(w1, 1, Ee * Dd * Hh);
    f2h_kernel<<<(Ee * Hh * Dd / 8 + 255) / 256, 256>>>(w2, 2, Ee * Hh * Dd);

    dim3 g1(Tt / 128, Hh / 128, Ee);
    mma_gemm<Dd, Hh, Dd, Hh, 1, true, Hh><<<g1, 256, SMEM_BYTES>>>(b1);

    dim3 g2(Tt / 128, Dd / 128, Ee);
    mma_gemm<Hh, Dd, Hh, Dd, 0, false, Dd><<<g2, 256, SMEM_BYTES>>>(b2);

    combine_kernel<<<(Tt * Dd / 4) / 256, 256>>>(out);

    int write_loss = (out_size > Tt * Dd) ? 1 : 0;
    loss_kernel<<<1, 256>>>(out, write_loss);
}

// round 13
// speedup vs baseline: 1.2605x; 1.2605x over previous
#include <cuda_runtime.h>
#include <cuda_fp16.h>
#include <math.h>

#define Tt 4096
#define Dd 1024
#define Hh 4096
#define Ee 8
#define Kk 2

// ---------------- device scratch ----------------
__device__ int    g_cnt[Ee];
__device__ int    g_slot[Ee * Tt];
__device__ float  g_wt[Tt * Kk];
__device__ float  g_probs[Tt * Ee];
__device__ __half g_xh[(size_t)Tt * Dd];          // x in fp16
__device__ __half g_w1h[(size_t)Ee * Dd * Hh];    // w1 in fp16
__device__ __half g_w2h[(size_t)Ee * Hh * Dd];    // w2 in fp16
__device__ __half g_h[(size_t)Tt * Kk * Hh];      // gelu(x@w1+b1) per slot (fp16)
__device__ float  g_y[(size_t)Tt * Kk * Dd];      // (h@w2+b2) per slot (fp32)

// ---------------- helpers ----------------
__device__ __forceinline__ unsigned smem_u32(const void* p) {
    unsigned a;
    asm("{ .reg .u64 t; cvta.to.shared.u64 t, %1; cvt.u32.u64 %0, t; }"
        : "=r"(a) : "l"(p));
    return a;
}
__device__ __forceinline__ void cp16(unsigned saddr, const void* g) {
    asm volatile("cp.async.cg.shared.global [%0], [%1], 16;"
                 :: "r"(saddr), "l"(g) : "memory");
}
__device__ __forceinline__ void mma_f16(float* d, const unsigned* a, const unsigned* b) {
    asm volatile(
        "mma.sync.aligned.m16n8k16.row.col.f32.f16.f16.f32 "
        "{%0,%1,%2,%3}, {%4,%5,%6,%7}, {%8,%9}, {%0,%1,%2,%3};"
        : "+f"(d[0]), "+f"(d[1]), "+f"(d[2]), "+f"(d[3])
        : "r"(a[0]), "r"(a[1]), "r"(a[2]), "r"(a[3]), "r"(b[0]), "r"(b[1]));
}
#define LDSM_X4(r, addr) \
    asm volatile("ldmatrix.sync.aligned.m8n8.x4.shared.b16 {%0,%1,%2,%3}, [%4];" \
        : "=r"((r)[0]), "=r"((r)[1]), "=r"((r)[2]), "=r"((r)[3]) : "r"(addr))
#define LDSM_X4_T(r, addr) \
    asm volatile("ldmatrix.sync.aligned.m8n8.x4.trans.shared.b16 {%0,%1,%2,%3}, [%4];" \
        : "=r"((r)[0]), "=r"((r)[1]), "=r"((r)[2]), "=r"((r)[3]) : "r"(addr))

// ---------------- zero counters ----------------
__global__ void zero_kernel() {
    int i = threadIdx.x;
    if (i < Ee) g_cnt[i] = 0;
}

// ---------------- f32 -> f16 convert (8 elems/thread) ----------------
__global__ void f2h_kernel(const float* __restrict__ s, int which, int n) {
    __half* d = (which == 0) ? g_xh : (which == 1) ? g_w1h : g_w2h;
    size_t i = ((size_t)blockIdx.x * blockDim.x + threadIdx.x) * 8;
    if (i >= (size_t)n) return;
    float4 v0 = *(const float4*)(s + i);
    float4 v1 = *(const float4*)(s + i + 4);
    __half2 h0 = __floats2half2_rn(v0.x, v0.y);
    __half2 h1 = __floats2half2_rn(v0.z, v0.w);
    __half2 h2 = __floats2half2_rn(v1.x, v1.y);
    __half2 h3 = __floats2half2_rn(v1.z, v1.w);
    uint4 o;
    o.x = *(unsigned*)&h0; o.y = *(unsigned*)&h1;
    o.z = *(unsigned*)&h2; o.w = *(unsigned*)&h3;
    *(uint4*)(d + i) = o;
}

// ---------------- router: 1 warp per token ----------------
__global__ void router_kernel(const float* __restrict__ x,
                              const float* __restrict__ rw) {
    int tid = threadIdx.x;
    int warp = tid >> 5, lane = tid & 31;
    int t = blockIdx.x * 8 + warp;

    const float* xr = x + (size_t)t * Dd;
    float acc[Ee];
#pragma unroll
    for (int e = 0; e < Ee; e++) acc[e] = 0.f;
    for (int d = lane; d < Dd; d += 32) {
        float xv = xr[d];
#pragma unroll
        for (int e = 0; e < Ee; e++) acc[e] += xv * rw[e * Dd + d];
    }
#pragma unroll
    for (int e = 0; e < Ee; e++)
#pragma unroll
        for (int off = 16; off > 0; off >>= 1)
            acc[e] += __shfl_xor_sync(0xffffffffu, acc[e], off);

    if (lane == 0) {
        float mx = acc[0];
#pragma unroll
        for (int e = 1; e < Ee; e++) mx = fmaxf(mx, acc[e]);
        float pe[Ee], s = 0.f;
#pragma unroll
        for (int e = 0; e < Ee; e++) { pe[e] = __expf(acc[e] - mx); s += pe[e]; }
        float inv = 1.f / s;
#pragma unroll
        for (int e = 0; e < Ee; e++) { pe[e] *= inv; g_probs[t * Ee + e] = pe[e]; }
        int i1 = 0;
#pragma unroll
        for (int e = 1; e < Ee; e++) if (pe[e] > pe[i1]) i1 = e;
        int i2 = (i1 == 0) ? 1 : 0;
#pragma unroll
        for (int e = 0; e < Ee; e++) if (e != i1 && pe[e] > pe[i2]) i2 = e;
        float denom = pe[i1] + pe[i2] + 1e-8f;
        int p1 = atomicAdd(&g_cnt[i1], 1);
        g_slot[i1 * Tt + p1] = t * 2 + 0;
        g_wt[t * 2 + 0] = pe[i1] / denom;
        int p2 = atomicAdd(&g_cnt[i2], 1);
        g_slot[i2 * Tt + p2] = t * 2 + 1;
        g_wt[t * 2 + 1] = pe[i2] / denom;
    }
}

// ---------------- fp16 mma.sync grouped GEMM ----------------
// CTA tile 128x128, K-chunk 64, 4 warps (2x2), warp tile 64x64,
// 128 threads, 255-reg budget, 2 CTAs/SM.
// 3-stage cp.async ring, ONE __syncthreads per chunk.
// Fragment double-buffering across k-steps (fits in 255 regs).
#define BK 64
#define A_BUF_B (128 * 144)                   // 18432 B
#define B_BUF_B (64 * 272)                    // 17408 B
#define STAGE_B (A_BUF_B + B_BUF_B)           // 35840 B
#define SM_SLOT_B (3 * STAGE_B)               // 107520
#define SMEM_BYTES (SM_SLOT_B + 512)          // 108032

template<int LDA, int LDW, int KTOT, int NTOT, int SHIFT, bool GELU, int LDO>
__global__ __launch_bounds__(128, 2)
void mma_gemm(const float* __restrict__ bias) {
    const int e = blockIdx.z;
    const int ne = g_cnt[e];
    const int row0 = blockIdx.x * 128;
    if (row0 >= ne) return;
    const int n0 = blockIdx.y * 128;

    extern __shared__ __align__(16) char smem[];
    int* slot_s = (int*)(smem + SM_SLOT_B);
    const unsigned sb = smem_u32(smem);

    const int tid = threadIdx.x, wid = tid >> 5, lane = tid & 31;
    const int g = lane >> 2, c = lane & 3;

    const __half* A = SHIFT ? g_xh : g_h;
    const __half* W = GELU ? g_w1h : g_w2h;

    {
        int r = row0 + tid;
        slot_s[tid] = g_slot[e * Tt + ((r < ne) ? r : (ne - 1))];
    }
    __syncthreads();

    // cp.async mappings (128 threads):
    // A: thread -> full row tid (8 x 16B), stride 144B (9x16B, lanes distinct mod 8)
    const __half* aSrc = A + (size_t)(slot_s[tid] >> SHIFT) * LDA;
    const unsigned aOff = tid * 144;
    // B: thread -> row (tid&63), half (tid>>6) (8 x 16B), stride 272B
    const int brow = tid & 63, bhalf = tid >> 6;
    const __half* bSrc = W + (size_t)e * KTOT * LDW + (size_t)brow * LDW + n0 + bhalf * 64;
    const unsigned bOff = A_BUF_B + brow * 272 + bhalf * 128;

    const int NK = KTOT / BK;

    // prologue: chunks 0,1 into stages 0,1
#pragma unroll
    for (int p = 0; p < 2; p++) {
        const unsigned s0 = sb + p * STAGE_B;
        const __half* ap = aSrc + (size_t)p * BK;
        const __half* bp = bSrc + (size_t)p * BK * LDW;
#pragma unroll
        for (int q = 0; q < 8; q++) cp16(s0 + aOff + q * 16, ap + q * 8);
#pragma unroll
        for (int q = 0; q < 8; q++) cp16(s0 + bOff + q * 16, bp + q * 8);
        asm volatile("cp.async.commit_group;" ::: "memory");
    }

    const int wm = (wid >> 1) * 64;
    const int wn = (wid & 1) * 64;

    // ldmatrix lane base offsets (within a stage)
    const unsigned aLd = (wm + (lane & 15)) * 144 + (lane >> 4) * 16;
    const unsigned bLd = A_BUF_B + (lane & 15) * 272 + wn * 2 + (lane >> 4) * 16;

    float acc[4][8][4];
#pragma unroll
    for (int mf = 0; mf < 4; mf++)
#pragma unroll
        for (int nf = 0; nf < 8; nf++)
#pragma unroll
            for (int v = 0; v < 4; v++) acc[mf][nf][v] = 0.f;

    // ping-pong fragment sets (fits: 128 acc + 64 frag < 255 regs)
    unsigned afr[2][4][4], bfr[2][4][4];

    int cs = 0;  // compute stage
    for (int i = 0; i < NK; i++) {
        if (i + 1 < NK) asm volatile("cp.async.wait_group 1;" ::: "memory");
        else            asm volatile("cp.async.wait_group 0;" ::: "memory");
        __syncthreads();

        // issue chunk i+2 into stage (cs+2)%3 — freed: all warps passed compute(i-1)
        if (i + 2 < NK) {
            const int ts = (cs == 0) ? 2 : cs - 1;
            const unsigned s0 = sb + ts * STAGE_B;
            const __half* ap = aSrc + (size_t)(i + 2) * BK;
            const __half* bp = bSrc + (size_t)(i + 2) * BK * LDW;
#pragma unroll
            for (int q = 0; q < 8; q++) cp16(s0 + aOff + q * 16, ap + q * 8);
#pragma unroll
            for (int q = 0; q < 8; q++) cp16(s0 + bOff + q * 16, bp + q * 8);
            asm volatile("cp.async.commit_group;" ::: "memory");
        }

        const unsigned ab = sb + cs * STAGE_B + aLd;
        const unsigned bb0 = sb + cs * STAGE_B + bLd;

        // prime k-step 0 fragments
#pragma unroll
        for (int mf = 0; mf < 4; mf++)
            LDSM_X4(afr[0][mf], ab + mf * (16 * 144));
#pragma unroll
        for (int j = 0; j < 4; j++)
            LDSM_X4_T(bfr[0][j], bb0 + j * 32);

#pragma unroll
        for (int ks = 0; ks < 4; ks++) {
            const int cur = ks & 1, nxt = cur ^ 1;
            if (ks < 3) {
#pragma unroll
                for (int mf = 0; mf < 4; mf++)
                    LDSM_X4(afr[nxt][mf], ab + mf * (16 * 144) + (ks + 1) * 32);
#pragma unroll
                for (int j = 0; j < 4; j++)
                    LDSM_X4_T(bfr[nxt][j], bb0 + (ks + 1) * (16 * 272) + j * 32);
            }
#pragma unroll
            for (int mf = 0; mf < 4; mf++)
#pragma unroll
                for (int nf = 0; nf < 8; nf++)
                    mma_f16(acc[mf][nf], afr[cur][mf], &bfr[cur][nf >> 1][(nf & 1) * 2]);
        }
        cs = (cs == 2) ? 0 : cs + 1;
    }

    // ---------------- epilogue ----------------
#pragma unroll
    for (int mf = 0; mf < 4; mf++) {
#pragma unroll
        for (int half_i = 0; half_i < 2; half_i++) {
            const int r = wm + mf * 16 + g + half_i * 8;
            if (row0 + r >= ne) continue;
            const int s = slot_s[r];
#pragma unroll
            for (int nf = 0; nf < 8; nf++) {
                const int col = wn + nf * 8 + c * 2;
                float v0 = acc[mf][nf][half_i * 2 + 0] + bias[e * NTOT + n0 + col];
                float v1 = acc[mf][nf][half_i * 2 + 1] + bias[e * NTOT + n0 + col + 1];
                if (GELU) {
                    v0 = 0.5f * v0 * (1.f + erff(v0 * 0.70710678118654752440f));
                    v1 = 0.5f * v1 * (1.f + erff(v1 * 0.70710678118654752440f));
                    __half2 h2 = __floats2half2_rn(v0, v1);
                    *(__half2*)(g_h + (size_t)s * LDO + n0 + col) = h2;
                } else {
                    float2 o; o.x = v0; o.y = v1;
                    *(float2*)(g_y + (size_t)s * LDO + n0 + col) = o;
                }
            }
        }
    }
}

// ---------------- combine ----------------
__global__ void combine_kernel(float* __restrict__ out) {
    int i = blockIdx.x * blockDim.x + threadIdx.x;
    int t = i >> 8;
    int d4 = i & 255;
    float w0 = g_wt[2 * t], w1 = g_wt[2 * t + 1];
    const float4* y = (const float4*)g_y;
    float4 a = y[(size_t)(2 * t) * 256 + d4];
    float4 b = y[(size_t)(2 * t + 1) * 256 + d4];
    float4 o;
    o.x = w0 * a.x + w1 * b.x;
    o.y = w0 * a.y + w1 * b.y;
    o.z = w0 * a.z + w1 * b.z;
    o.w = w0 * a.w + w1 * b.w;
    ((float4*)out)[i] = o;
}

// ---------------- load-balancing loss ----------------
__global__ void loss_kernel(float* __restrict__ out, int write_loss) {
    __shared__ float sred[256 * Ee];
    int tid = threadIdx.x;
    float l[Ee];
#pragma unroll
    for (int e = 0; e < Ee; e++) l[e] = 0.f;
    for (int t = tid; t < Tt; t += 256)
#pragma unroll
        for (int e = 0; e < Ee; e++) l[e] += g_probs[t * Ee + e];
#pragma unroll
    for (int e = 0; e < Ee; e++) sred[tid * Ee + e] = l[e];
    __syncthreads();
    for (int s = 128; s > 0; s >>= 1) {
        if (tid < s)
#pragma unroll
            for (int e = 0; e < Ee; e++)
                sred[tid * Ee + e] += sred[(tid + s) * Ee + e];
        __syncthreads();
    }
    if (tid == 0 && write_loss) {
        float loss = 0.f;
        for (int e = 0; e < Ee; e++) {
            float mean_p = sred[e] / (float)Tt;
            float frac = (float)g_cnt[e] / (float)(Tt * Kk);
            loss += mean_p * frac;
        }
        out[(size_t)Tt * Dd] = loss * (float)Ee;
    }
}

// ---------------- launch ----------------
extern "C" void kernel_launch(void* const* d_in, const int* in_sizes, int n_in,
                              void* d_out, int out_size) {
    const float* x  = (const float*)d_in[0];
    const float* rw = (const float*)d_in[1];
    const float* w1 = (const float*)d_in[2];
    const float* b1 = (const float*)d_in[3];
    const float* w2 = (const float*)d_in[4];
    const float* b2 = (const float*)d_in[5];
    float* out = (float*)d_out;

    cudaFuncSetAttribute(mma_gemm<Dd, Hh, Dd, Hh, 1, true, Hh>,
                         cudaFuncAttributeMaxDynamicSharedMemorySize, SMEM_BYTES);
    cudaFuncSetAttribute(mma_gemm<Hh, Dd, Hh, Dd, 0, false, Dd>,
                         cudaFuncAttributeMaxDynamicSharedMemorySize, SMEM_BYTES);

    zero_kernel<<<1, 32>>>();
    router_kernel<<<Tt / 8, 256>>>(x, rw);

    // f32 -> f16 conversions
    f2h_kernel<<<(Tt * Dd / 8 + 255) / 256, 256>>>(x, 0, Tt * Dd);
    f2h_kernel<<<(Ee * Dd * Hh / 8 + 255) / 256, 256>>>(w1, 1, Ee * Dd * Hh);
    f2h_kernel<<<(Ee * Hh * Dd / 8 + 255) / 256, 256>>>(w2, 2, Ee * Hh * Dd);

    dim3 g1(Tt / 128, Hh / 128, Ee);
    mma_gemm<Dd, Hh, Dd, Hh, 1, true, Hh><<<g1, 128, SMEM_BYTES>>>(b1);

    dim3 g2(Tt / 128, Dd / 128, Ee);
    mma_gemm<Hh, Dd, Hh, Dd, 0, false, Dd><<<g2, 128, SMEM_BYTES>>>(b2);

    combine_kernel<<<(Tt * Dd / 4) / 256, 256>>>(out);

    int write_loss = (out_size > Tt * Dd) ? 1 : 0;
    loss_kernel<<<1, 256>>>(out, write_loss);
}

// round 14
// speedup vs baseline: 1.4737x; 1.1691x over previous
#include <cuda_runtime.h>
#include <cuda_fp16.h>
#include <math.h>

#define Tt 4096
#define Dd 1024
#define Hh 4096
#define Ee 8
#define Kk 2

// ---------------- device scratch ----------------
__device__ int    g_cnt[Ee];
__device__ int    g_slot[Ee * Tt];
__device__ float  g_wt[Tt * Kk];
__device__ float  g_probs[Tt * Ee];
__device__ __half g_xh[(size_t)Tt * Dd];          // x in fp16
__device__ __half g_w1h[(size_t)Ee * Dd * Hh];    // w1 in fp16
__device__ __half g_w2h[(size_t)Ee * Hh * Dd];    // w2 in fp16
__device__ __half g_h[(size_t)Tt * Kk * Hh];      // gelu(x@w1+b1) per slot (fp16)
__device__ float  g_y[(size_t)Tt * Kk * Dd];      // (h@w2+b2) per slot (fp32)

// ---------------- helpers ----------------
__device__ __forceinline__ unsigned smem_u32(const void* p) {
    unsigned a;
    asm("{ .reg .u64 t; cvta.to.shared.u64 t, %1; cvt.u32.u64 %0, t; }"
        : "=r"(a) : "l"(p));
    return a;
}
__device__ __forceinline__ void cp16(unsigned saddr, const void* g) {
    asm volatile("cp.async.cg.shared.global [%0], [%1], 16;"
                 :: "r"(saddr), "l"(g) : "memory");
}
__device__ __forceinline__ void mma_f16(float* d, const unsigned* a, const unsigned* b) {
    asm volatile(
        "mma.sync.aligned.m16n8k16.row.col.f32.f16.f16.f32 "
        "{%0,%1,%2,%3}, {%4,%5,%6,%7}, {%8,%9}, {%0,%1,%2,%3};"
        : "+f"(d[0]), "+f"(d[1]), "+f"(d[2]), "+f"(d[3])
        : "r"(a[0]), "r"(a[1]), "r"(a[2]), "r"(a[3]), "r"(b[0]), "r"(b[1]));
}
#define LDSM_X4(r, addr) \
    asm volatile("ldmatrix.sync.aligned.m8n8.x4.shared.b16 {%0,%1,%2,%3}, [%4];" \
        : "=r"((r)[0]), "=r"((r)[1]), "=r"((r)[2]), "=r"((r)[3]) : "r"(addr))
#define LDSM_X4_T(r, addr) \
    asm volatile("ldmatrix.sync.aligned.m8n8.x4.trans.shared.b16 {%0,%1,%2,%3}, [%4];" \
        : "=r"((r)[0]), "=r"((r)[1]), "=r"((r)[2]), "=r"((r)[3]) : "r"(addr))

// ---------------- zero counters ----------------
__global__ void zero_kernel() {
    int i = threadIdx.x;
    if (i < Ee) g_cnt[i] = 0;
}

// ---------------- f32 -> f16 convert (weights; 8 elems/thread) ----------------
__global__ void f2h_kernel(const float* __restrict__ s, int which, int n) {
    __half* d = (which == 1) ? g_w1h : g_w2h;
    size_t i = ((size_t)blockIdx.x * blockDim.x + threadIdx.x) * 8;
    if (i >= (size_t)n) return;
    float4 v0 = *(const float4*)(s + i);
    float4 v1 = *(const float4*)(s + i + 4);
    __half2 h0 = __floats2half2_rn(v0.x, v0.y);
    __half2 h1 = __floats2half2_rn(v0.z, v0.w);
    __half2 h2 = __floats2half2_rn(v1.x, v1.y);
    __half2 h3 = __floats2half2_rn(v1.z, v1.w);
    uint4 o;
    o.x = *(unsigned*)&h0; o.y = *(unsigned*)&h1;
    o.z = *(unsigned*)&h2; o.w = *(unsigned*)&h3;
    *(uint4*)(d + i) = o;
}

// ---------------- router (+ fused f2h of x): 1 warp per token ----------------
__global__ void router_kernel(const float* __restrict__ x,
                              const float* __restrict__ rw) {
    int tid = threadIdx.x;
    int warp = tid >> 5, lane = tid & 31;
    int t = blockIdx.x * 8 + warp;

    const float* xr = x + (size_t)t * Dd;
    __half* xh = g_xh + (size_t)t * Dd;
    float acc[Ee];
#pragma unroll
    for (int e = 0; e < Ee; e++) acc[e] = 0.f;
    for (int d = lane; d < Dd; d += 32) {
        float xv = xr[d];
        xh[d] = __float2half_rn(xv);          // fused f2h(x)
#pragma unroll
        for (int e = 0; e < Ee; e++) acc[e] += xv * rw[e * Dd + d];
    }
#pragma unroll
    for (int e = 0; e < Ee; e++)
#pragma unroll
        for (int off = 16; off > 0; off >>= 1)
            acc[e] += __shfl_xor_sync(0xffffffffu, acc[e], off);

    if (lane == 0) {
        float mx = acc[0];
#pragma unroll
        for (int e = 1; e < Ee; e++) mx = fmaxf(mx, acc[e]);
        float pe[Ee], s = 0.f;
#pragma unroll
        for (int e = 0; e < Ee; e++) { pe[e] = __expf(acc[e] - mx); s += pe[e]; }
        float inv = 1.f / s;
#pragma unroll
        for (int e = 0; e < Ee; e++) { pe[e] *= inv; g_probs[t * Ee + e] = pe[e]; }
        int i1 = 0;
#pragma unroll
        for (int e = 1; e < Ee; e++) if (pe[e] > pe[i1]) i1 = e;
        int i2 = (i1 == 0) ? 1 : 0;
#pragma unroll
        for (int e = 0; e < Ee; e++) if (e != i1 && pe[e] > pe[i2]) i2 = e;
        float denom = pe[i1] + pe[i2] + 1e-8f;
        int p1 = atomicAdd(&g_cnt[i1], 1);
        g_slot[i1 * Tt + p1] = t * 2 + 0;
        g_wt[t * 2 + 0] = pe[i1] / denom;
        int p2 = atomicAdd(&g_cnt[i2], 1);
        g_slot[i2 * Tt + p2] = t * 2 + 1;
        g_wt[t * 2 + 1] = pe[i2] / denom;
    }
}

// ---------------- fp16 mma.sync grouped GEMM (r11 proven-best config) ----------------
// CTA tile 128x128, K-chunk 64, 8 warps (2x4), warp tile 64x32, 2 CTAs/SM.
// 3-stage cp.async ring, ONE __syncthreads per chunk.
#define BK 64
#define A_BUF_B (128 * 144)                   // 18432 B
#define B_BUF_B (64 * 272)                    // 17408 B
#define STAGE_B (A_BUF_B + B_BUF_B)           // 35840 B
#define SM_SLOT_B (3 * STAGE_B)               // 107520
#define SMEM_BYTES (SM_SLOT_B + 512)          // 108032

template<int LDA, int LDW, int KTOT, int NTOT, int SHIFT, bool GELU, int LDO>
__global__ __launch_bounds__(256, 2)
void mma_gemm(const float* __restrict__ bias) {
    const int e = blockIdx.z;
    const int ne = g_cnt[e];
    const int row0 = blockIdx.x * 128;
    if (row0 >= ne) return;
    const int n0 = blockIdx.y * 128;

    extern __shared__ __align__(16) char smem[];
    int* slot_s = (int*)(smem + SM_SLOT_B);
    const unsigned sb = smem_u32(smem);

    const int tid = threadIdx.x, wid = tid >> 5, lane = tid & 31;
    const int g = lane >> 2, c = lane & 3;

    const __half* A = SHIFT ? g_xh : g_h;
    const __half* W = GELU ? g_w1h : g_w2h;

    if (tid < 128) {
        int r = row0 + tid;
        slot_s[tid] = g_slot[e * Tt + ((r < ne) ? r : (ne - 1))];
    }
    __syncthreads();

    // cp.async mappings: A 2 thr/row (4x16B), B 4 thr/row (4x16B)
    const int arow = tid >> 1, acb = (tid & 1) * 4;
    const __half* aSrc = A + (size_t)(slot_s[arow] >> SHIFT) * LDA + acb * 8;
    const unsigned aOff = arow * 144 + acb * 16;
    const int brow = tid >> 2, bcb = (tid & 3) * 4;
    const __half* bSrc = W + (size_t)e * KTOT * LDW + (size_t)brow * LDW + n0 + bcb * 8;
    const unsigned bOff = A_BUF_B + brow * 272 + bcb * 16;

    const int NK = KTOT / BK;

    // prologue: chunks 0,1 into stages 0,1
#pragma unroll
    for (int p = 0; p < 2; p++) {
        const unsigned s0 = sb + p * STAGE_B;
        const __half* ap = aSrc + (size_t)p * BK;
        const __half* bp = bSrc + (size_t)p * BK * LDW;
#pragma unroll
        for (int q = 0; q < 4; q++) cp16(s0 + aOff + q * 16, ap + q * 8);
#pragma unroll
        for (int q = 0; q < 4; q++) cp16(s0 + bOff + q * 16, bp + q * 8);
        asm volatile("cp.async.commit_group;" ::: "memory");
    }

    const int wm = (wid >> 2) * 64;
    const int wn = (wid & 3) * 32;

    // ldmatrix lane base offsets (within a stage)
    const unsigned aLd = (wm + (lane & 15)) * 144 + (lane >> 4) * 16;
    const unsigned bLd = A_BUF_B + (lane & 15) * 272 + wn * 2 + (lane >> 4) * 16;

    float acc[4][4][4];
#pragma unroll
    for (int mf = 0; mf < 4; mf++)
#pragma unroll
        for (int nf = 0; nf < 4; nf++)
#pragma unroll
            for (int v = 0; v < 4; v++) acc[mf][nf][v] = 0.f;

    int cs = 0;  // compute stage
    for (int i = 0; i < NK; i++) {
        if (i + 1 < NK) asm volatile("cp.async.wait_group 1;" ::: "memory");
        else            asm volatile("cp.async.wait_group 0;" ::: "memory");
        __syncthreads();

        // issue chunk i+2 into stage (cs+2)%3 — freed: all warps passed compute(i-1)
        if (i + 2 < NK) {
            const int ts = (cs == 0) ? 2 : cs - 1;
            const unsigned s0 = sb + ts * STAGE_B;
            const __half* ap = aSrc + (size_t)(i + 2) * BK;
            const __half* bp = bSrc + (size_t)(i + 2) * BK * LDW;
#pragma unroll
            for (int q = 0; q < 4; q++) cp16(s0 + aOff + q * 16, ap + q * 8);
#pragma unroll
            for (int q = 0; q < 4; q++) cp16(s0 + bOff + q * 16, bp + q * 8);
            asm volatile("cp.async.commit_group;" ::: "memory");
        }

        const unsigned ab = sb + cs * STAGE_B + aLd;
        const unsigned bb0 = sb + cs * STAGE_B + bLd;
#pragma unroll
        for (int ks = 0; ks < 4; ks++) {
            unsigned a[4][4], bb[2][4];
#pragma unroll
            for (int mf = 0; mf < 4; mf++)
                LDSM_X4(a[mf], ab + mf * (16 * 144) + ks * 32);
            LDSM_X4_T(bb[0], bb0 + ks * (16 * 272));
            LDSM_X4_T(bb[1], bb0 + ks * (16 * 272) + 32);
#pragma unroll
            for (int mf = 0; mf < 4; mf++)
#pragma unroll
                for (int nf = 0; nf < 4; nf++)
                    mma_f16(acc[mf][nf], a[mf], &bb[nf >> 1][(nf & 1) * 2]);
        }
        cs = (cs == 2) ? 0 : cs + 1;
    }

    // ---------------- epilogue ----------------
#pragma unroll
    for (int mf = 0; mf < 4; mf++) {
#pragma unroll
        for (int half_i = 0; half_i < 2; half_i++) {
            const int r = wm + mf * 16 + g + half_i * 8;
            if (row0 + r >= ne) continue;
            const int s = slot_s[r];
#pragma unroll
            for (int nf = 0; nf < 4; nf++) {
                const int col = wn + nf * 8 + c * 2;
                float v0 = acc[mf][nf][half_i * 2 + 0] + bias[e * NTOT + n0 + col];
                float v1 = acc[mf][nf][half_i * 2 + 1] + bias[e * NTOT + n0 + col + 1];
                if (GELU) {
                    v0 = 0.5f * v0 * (1.f + erff(v0 * 0.70710678118654752440f));
                    v1 = 0.5f * v1 * (1.f + erff(v1 * 0.70710678118654752440f));
                    __half2 h2 = __floats2half2_rn(v0, v1);
                    *(__half2*)(g_h + (size_t)s * LDO + n0 + col) = h2;
                } else {
                    float2 o; o.x = v0; o.y = v1;
                    *(float2*)(g_y + (size_t)s * LDO + n0 + col) = o;
                }
            }
        }
    }
}

// ---------------- combine ----------------
__global__ void combine_kernel(float* __restrict__ out) {
    int i = blockIdx.x * blockDim.x + threadIdx.x;
    int t = i >> 8;
    int d4 = i & 255;
    float w0 = g_wt[2 * t], w1 = g_wt[2 * t + 1];
    const float4* y = (const float4*)g_y;
    float4 a = y[(size_t)(2 * t) * 256 + d4];
    float4 b = y[(size_t)(2 * t + 1) * 256 + d4];
    float4 o;
    o.x = w0 * a.x + w1 * b.x;
    o.y = w0 * a.y + w1 * b.y;
    o.z = w0 * a.z + w1 * b.z;
    o.w = w0 * a.w + w1 * b.w;
    ((float4*)out)[i] = o;
}

// ---------------- load-balancing loss ----------------
__global__ void loss_kernel(float* __restrict__ out, int write_loss) {
    __shared__ float sred[256 * Ee];
    int tid = threadIdx.x;
    float l[Ee];
#pragma unroll
    for (int e = 0; e < Ee; e++) l[e] = 0.f;
    for (int t = tid; t < Tt; t += 256)
#pragma unroll
        for (int e = 0; e < Ee; e++) l[e] += g_probs[t * Ee + e];
#pragma unroll
    for (int e = 0; e < Ee; e++) sred[tid * Ee + e] = l[e];
    __syncthreads();
    for (int s = 128; s > 0; s >>= 1) {
        if (tid < s)
#pragma unroll
            for (int e = 0; e < Ee; e++)
                sred[tid * Ee + e] += sred[(tid + s) * Ee + e];
        __syncthreads();
    }
    if (tid == 0 && write_loss) {
        float loss = 0.f;
        for (int e = 0; e < Ee; e++) {
            float mean_p = sred[e] / (float)Tt;
            float frac = (float)g_cnt[e] / (float)(Tt * Kk);
            loss += mean_p * frac;
        }
        out[(size_t)Tt * Dd] = loss * (float)Ee;
    }
}

// ---------------- launch ----------------
// Launch order puts gemm1 at process-launch #6 so ncu (-s 5 -c 1) profiles it.
extern "C" void kernel_launch(void* const* d_in, const int* in_sizes, int n_in,
                              void* d_out, int out_size) {
    const float* x  = (const float*)d_in[0];
    const float* rw = (const float*)d_in[1];
    const float* w1 = (const float*)d_in[2];
    const float* b1 = (const float*)d_in[3];
    const float* w2 = (const float*)d_in[4];
    const float* b2 = (const float*)d_in[5];
    float* out = (float*)d_out;

    cudaFuncSetAttribute(mma_gemm<Dd, Hh, Dd, Hh, 1, true, Hh>,
                         cudaFuncAttributeMaxDynamicSharedMemorySize, SMEM_BYTES);
    cudaFuncSetAttribute(mma_gemm<Hh, Dd, Hh, Dd, 0, false, Dd>,
                         cudaFuncAttributeMaxDynamicSharedMemorySize, SMEM_BYTES);

    zero_kernel<<<1, 32>>>();
    f2h_kernel<<<(Ee * Dd * Hh / 8 + 255) / 256, 256>>>(w1, 1, Ee * Dd * Hh);
    f2h_kernel<<<(Ee * Hh * Dd / 8 + 255) / 256, 256>>>(w2, 2, Ee * Hh * Dd);
    router_kernel<<<Tt / 8, 256>>>(x, rw);   // also emits g_xh

    dim3 g1(Tt / 128, Hh / 128, Ee);
    mma_gemm<Dd, Hh, Dd, Hh, 1, true, Hh><<<g1, 256, SMEM_BYTES>>>(b1);

    dim3 g2(Tt / 128, Dd / 128, Ee);
    mma_gemm<Hh, Dd, Hh, Dd, 0, false, Dd><<<g2, 256, SMEM_BYTES>>>(b2);

    combine_kernel<<<(Tt * Dd / 4) / 256, 256>>>(out);

    int write_loss = (out_size > Tt * Dd) ? 1 : 0;
    loss_kernel<<<1, 256>>>(out, write_loss);
}

// round 16
// speedup vs baseline: 1.4785x; 1.0033x over previous
#include <cuda_runtime.h>
#include <cuda_fp16.h>
#include <math.h>

#define Tt 4096
#define Dd 1024
#define Hh 4096
#define Ee 8
#define Kk 2

// ---------------- device scratch ----------------
__device__ int    g_cnt[Ee];
__device__ int    g_slot[Ee * Tt];
__device__ float  g_wt[Tt * Kk];
__device__ float  g_probs[Tt * Ee];
__device__ __half g_xh[(size_t)Tt * Dd];          // x in fp16
__device__ __half g_w1h[(size_t)Ee * Dd * Hh];    // w1 in fp16
__device__ __half g_w2h[(size_t)Ee * Hh * Dd];    // w2 in fp16
__device__ __half g_h[(size_t)Tt * Kk * Hh];      // gelu(x@w1+b1) per slot (fp16)
__device__ float  g_y[(size_t)Tt * Kk * Dd];      // (h@w2+b2) per slot (fp32)

// ---------------- helpers ----------------
__device__ __forceinline__ unsigned smem_u32(const void* p) {
    unsigned a;
    asm("{ .reg .u64 t; cvta.to.shared.u64 t, %1; cvt.u32.u64 %0, t; }"
        : "=r"(a) : "l"(p));
    return a;
}
__device__ __forceinline__ void cp16(unsigned saddr, const void* g) {
    asm volatile("cp.async.cg.shared.global [%0], [%1], 16;"
                 :: "r"(saddr), "l"(g) : "memory");
}
__device__ __forceinline__ void mma_f16(float* d, const unsigned* a, const unsigned* b) {
    asm volatile(
        "mma.sync.aligned.m16n8k16.row.col.f32.f16.f16.f32 "
        "{%0,%1,%2,%3}, {%4,%5,%6,%7}, {%8,%9}, {%0,%1,%2,%3};"
        : "+f"(d[0]), "+f"(d[1]), "+f"(d[2]), "+f"(d[3])
        : "r"(a[0]), "r"(a[1]), "r"(a[2]), "r"(a[3]), "r"(b[0]), "r"(b[1]));
}
#define LDSM_X4(r, addr) \
    asm volatile("ldmatrix.sync.aligned.m8n8.x4.shared.b16 {%0,%1,%2,%3}, [%4];" \
        : "=r"((r)[0]), "=r"((r)[1]), "=r"((r)[2]), "=r"((r)[3]) : "r"(addr))
#define LDSM_X4_T(r, addr) \
    asm volatile("ldmatrix.sync.aligned.m8n8.x4.trans.shared.b16 {%0,%1,%2,%3}, [%4];" \
        : "=r"((r)[0]), "=r"((r)[1]), "=r"((r)[2]), "=r"((r)[3]) : "r"(addr))

// ---------------- f32 -> f16 weight convert; w1 variant also zeroes g_cnt ----------------
__global__ void f2h_kernel(const float* __restrict__ s, int which, int n) {
    if (which == 1 && blockIdx.x == 0 && threadIdx.x < Ee)
        g_cnt[threadIdx.x] = 0;
    __half* d = (which == 1) ? g_w1h : g_w2h;
    size_t i = ((size_t)blockIdx.x * blockDim.x + threadIdx.x) * 8;
    if (i >= (size_t)n) return;
    float4 v0 = *(const float4*)(s + i);
    float4 v1 = *(const float4*)(s + i + 4);
    __half2 h0 = __floats2half2_rn(v0.x, v0.y);
    __half2 h1 = __floats2half2_rn(v0.z, v0.w);
    __half2 h2 = __floats2half2_rn(v1.x, v1.y);
    __half2 h3 = __floats2half2_rn(v1.z, v1.w);
    uint4 o;
    o.x = *(unsigned*)&h0; o.y = *(unsigned*)&h1;
    o.z = *(unsigned*)&h2; o.w = *(unsigned*)&h3;
    *(uint4*)(d + i) = o;
}

// ---------------- router (+ fused f2h of x): 1 warp per token, float4 loads ----------------
__global__ void router_kernel(const float* __restrict__ x,
                              const float* __restrict__ rw) {
    int tid = threadIdx.x;
    int warp = tid >> 5, lane = tid & 31;
    int t = blockIdx.x * 8 + warp;

    const float4* xr4 = (const float4*)(x + (size_t)t * Dd);
    const float4* rw4 = (const float4*)rw;            // [E][Dd/4]
    uint2* xh2 = (uint2*)(g_xh + (size_t)t * Dd);
    float acc[Ee];
#pragma unroll
    for (int e = 0; e < Ee; e++) acc[e] = 0.f;
#pragma unroll
    for (int d4 = lane, it = 0; it < Dd / 4 / 32; d4 += 32, it++) {
        float4 xv = xr4[d4];
        __half2 h0 = __floats2half2_rn(xv.x, xv.y);
        __half2 h1 = __floats2half2_rn(xv.z, xv.w);
        uint2 u; u.x = *(unsigned*)&h0; u.y = *(unsigned*)&h1;
        xh2[d4] = u;                                   // fused f2h(x)
#pragma unroll
        for (int e = 0; e < Ee; e++) {
            float4 wv = rw4[e * (Dd / 4) + d4];
            acc[e] += xv.x * wv.x + xv.y * wv.y + xv.z * wv.z + xv.w * wv.w;
        }
    }
#pragma unroll
    for (int e = 0; e < Ee; e++)
#pragma unroll
        for (int off = 16; off > 0; off >>= 1)
            acc[e] += __shfl_xor_sync(0xffffffffu, acc[e], off);

    if (lane == 0) {
        float mx = acc[0];
#pragma unroll
        for (int e = 1; e < Ee; e++) mx = fmaxf(mx, acc[e]);
        float pe[Ee], s = 0.f;
#pragma unroll
        for (int e = 0; e < Ee; e++) { pe[e] = __expf(acc[e] - mx); s += pe[e]; }
        float inv = 1.f / s;
#pragma unroll
        for (int e = 0; e < Ee; e++) { pe[e] *= inv; g_probs[t * Ee + e] = pe[e]; }
        int i1 = 0;
#pragma unroll
        for (int e = 1; e < Ee; e++) if (pe[e] > pe[i1]) i1 = e;
        int i2 = (i1 == 0) ? 1 : 0;
#pragma unroll
        for (int e = 0; e < Ee; e++) if (e != i1 && pe[e] > pe[i2]) i2 = e;
        float denom = pe[i1] + pe[i2] + 1e-8f;
        int p1 = atomicAdd(&g_cnt[i1], 1);
        g_slot[i1 * Tt + p1] = t * 2 + 0;
        g_wt[t * 2 + 0] = pe[i1] / denom;
        int p2 = atomicAdd(&g_cnt[i2], 1);
        g_slot[i2 * Tt + p2] = t * 2 + 1;
        g_wt[t * 2 + 1] = pe[i2] / denom;
    }
}

// ---------------- fp16 mma.sync grouped GEMM (proven-best config, unchanged) ----------------
// CTA tile 128x128, K-chunk 64, 8 warps (2x4), warp tile 64x32, 2 CTAs/SM.
// 3-stage cp.async ring, ONE __syncthreads per chunk.
#define BK 64
#define A_BUF_B (128 * 144)                   // 18432 B
#define B_BUF_B (64 * 272)                    // 17408 B
#define STAGE_B (A_BUF_B + B_BUF_B)           // 35840 B
#define SM_SLOT_B (3 * STAGE_B)               // 107520
#define SMEM_BYTES (SM_SLOT_B + 512)          // 108032

template<int LDA, int LDW, int KTOT, int NTOT, int SHIFT, bool GELU, int LDO>
__global__ __launch_bounds__(256, 2)
void mma_gemm(const float* __restrict__ bias) {
    const int e = blockIdx.z;
    const int ne = g_cnt[e];
    const int row0 = blockIdx.x * 128;
    if (row0 >= ne) return;
    const int n0 = blockIdx.y * 128;

    extern __shared__ __align__(16) char smem[];
    int* slot_s = (int*)(smem + SM_SLOT_B);
    const unsigned sb = smem_u32(smem);

    const int tid = threadIdx.x, wid = tid >> 5, lane = tid & 31;
    const int g = lane >> 2, c = lane & 3;

    const __half* A = SHIFT ? g_xh : g_h;
    const __half* W = GELU ? g_w1h : g_w2h;

    if (tid < 128) {
        int r = row0 + tid;
        slot_s[tid] = g_slot[e * Tt + ((r < ne) ? r : (ne - 1))];
    }
    __syncthreads();

    // cp.async mappings: A 2 thr/row (4x16B), B 4 thr/row (4x16B)
    const int arow = tid >> 1, acb = (tid & 1) * 4;
    const __half* aSrc = A + (size_t)(slot_s[arow] >> SHIFT) * LDA + acb * 8;
    const unsigned aOff = arow * 144 + acb * 16;
    const int brow = tid >> 2, bcb = (tid & 3) * 4;
    const __half* bSrc = W + (size_t)e * KTOT * LDW + (size_t)brow * LDW + n0 + bcb * 8;
    const unsigned bOff = A_BUF_B + brow * 272 + bcb * 16;

    const int NK = KTOT / BK;

    // prologue: chunks 0,1 into stages 0,1
#pragma unroll
    for (int p = 0; p < 2; p++) {
        const unsigned s0 = sb + p * STAGE_B;
        const __half* ap = aSrc + (size_t)p * BK;
        const __half* bp = bSrc + (size_t)p * BK * LDW;
#pragma unroll
        for (int q = 0; q < 4; q++) cp16(s0 + aOff + q * 16, ap + q * 8);
#pragma unroll
        for (int q = 0; q < 4; q++) cp16(s0 + bOff + q * 16, bp + q * 8);
        asm volatile("cp.async.commit_group;" ::: "memory");
    }

    const int wm = (wid >> 2) * 64;
    const int wn = (wid & 3) * 32;

    // ldmatrix lane base offsets (within a stage)
    const unsigned aLd = (wm + (lane & 15)) * 144 + (lane >> 4) * 16;
    const unsigned bLd = A_BUF_B + (lane & 15) * 272 + wn * 2 + (lane >> 4) * 16;

    float acc[4][4][4];
#pragma unroll
    for (int mf = 0; mf < 4; mf++)
#pragma unroll
        for (int nf = 0; nf < 4; nf++)
#pragma unroll
            for (int v = 0; v < 4; v++) acc[mf][nf][v] = 0.f;

    int cs = 0;  // compute stage
    for (int i = 0; i < NK; i++) {
        if (i + 1 < NK) asm volatile("cp.async.wait_group 1;" ::: "memory");
        else            asm volatile("cp.async.wait_group 0;" ::: "memory");
        __syncthreads();

        // issue chunk i+2 into stage (cs+2)%3 — freed: all warps passed compute(i-1)
        if (i + 2 < NK) {
            const int ts = (cs == 0) ? 2 : cs - 1;
            const unsigned s0 = sb + ts * STAGE_B;
            const __half* ap = aSrc + (size_t)(i + 2) * BK;
            const __half* bp = bSrc + (size_t)(i + 2) * BK * LDW;
#pragma unroll
            for (int q = 0; q < 4; q++) cp16(s0 + aOff + q * 16, ap + q * 8);
#pragma unroll
            for (int q = 0; q < 4; q++) cp16(s0 + bOff + q * 16, bp + q * 8);
            asm volatile("cp.async.commit_group;" ::: "memory");
        }

        const unsigned ab = sb + cs * STAGE_B + aLd;
        const unsigned bb0 = sb + cs * STAGE_B + bLd;
#pragma unroll
        for (int ks = 0; ks < 4; ks++) {
            unsigned a[4][4], bb[2][4];
#pragma unroll
            for (int mf = 0; mf < 4; mf++)
                LDSM_X4(a[mf], ab + mf * (16 * 144) + ks * 32);
            LDSM_X4_T(bb[0], bb0 + ks * (16 * 272));
            LDSM_X4_T(bb[1], bb0 + ks * (16 * 272) + 32);
#pragma unroll
            for (int mf = 0; mf < 4; mf++)
#pragma unroll
                for (int nf = 0; nf < 4; nf++)
                    mma_f16(acc[mf][nf], a[mf], &bb[nf >> 1][(nf & 1) * 2]);
        }
        cs = (cs == 2) ? 0 : cs + 1;
    }

    // ---------------- epilogue ----------------
#pragma unroll
    for (int mf = 0; mf < 4; mf++) {
#pragma unroll
        for (int half_i = 0; half_i < 2; half_i++) {
            const int r = wm + mf * 16 + g + half_i * 8;
            if (row0 + r >= ne) continue;
            const int s = slot_s[r];
#pragma unroll
            for (int nf = 0; nf < 4; nf++) {
                const int col = wn + nf * 8 + c * 2;
                float v0 = acc[mf][nf][half_i * 2 + 0] + bias[e * NTOT + n0 + col];
                float v1 = acc[mf][nf][half_i * 2 + 1] + bias[e * NTOT + n0 + col + 1];
                if (GELU) {
                    v0 = 0.5f * v0 * (1.f + erff(v0 * 0.70710678118654752440f));
                    v1 = 0.5f * v1 * (1.f + erff(v1 * 0.70710678118654752440f));
                    __half2 h2 = __floats2half2_rn(v0, v1);
                    *(__half2*)(g_h + (size_t)s * LDO + n0 + col) = h2;
                } else {
                    float2 o; o.x = v0; o.y = v1;
                    *(float2*)(g_y + (size_t)s * LDO + n0 + col) = o;
                }
            }
        }
    }
}

// ---------------- combine ----------------
__global__ void combine_kernel(float* __restrict__ out) {
    int i = blockIdx.x * blockDim.x + threadIdx.x;
    int t = i >> 8;
    int d4 = i & 255;
    float w0 = g_wt[2 * t], w1 = g_wt[2 * t + 1];
    const float4* y = (const float4*)g_y;
    float4 a = y[(size_t)(2 * t) * 256 + d4];
    float4 b = y[(size_t)(2 * t + 1) * 256 + d4];
    float4 o;
    o.x = w0 * a.x + w1 * b.x;
    o.y = w0 * a.y + w1 * b.y;
    o.z = w0 * a.z + w1 * b.z;
    o.w = w0 * a.w + w1 * b.w;
    ((float4*)out)[i] = o;
}

// ---------------- load-balancing loss ----------------
__global__ void loss_kernel(float* __restrict__ out, int write_loss) {
    __shared__ float sred[256 * Ee];
    int tid = threadIdx.x;
    float l[Ee];
#pragma unroll
    for (int e = 0; e < Ee; e++) l[e] = 0.f;
    for (int t = tid; t < Tt; t += 256)
#pragma unroll
        for (int e = 0; e < Ee; e++) l[e] += g_probs[t * Ee + e];
#pragma unroll
    for (int e = 0; e < Ee; e++) sred[tid * Ee + e] = l[e];
    __syncthreads();
    for (int s = 128; s > 0; s >>= 1) {
        if (tid < s)
#pragma unroll
            for (int e = 0; e < Ee; e++)
                sred[tid * Ee + e] += sred[(tid + s) * Ee + e];
        __syncthreads();
    }
    if (tid == 0 && write_loss) {
        float loss = 0.f;
        for (int e = 0; e < Ee; e++) {
            float mean_p = sred[e] / (float)Tt;
            float frac = (float)g_cnt[e] / (float)(Tt * Kk);
            loss += mean_p * frac;
        }
        out[(size_t)Tt * Dd] = loss * (float)Ee;
    }
}

// ---------------- launch ----------------
// My 4th launch = process launch #6 (2 harness extras) => ncu -s 5 profiles gemm1.
extern "C" void kernel_launch(void* const* d_in, const int* in_sizes, int n_in,
                              void* d_out, int out_size) {
    const float* x  = (const float*)d_in[0];
    const float* rw = (const float*)d_in[1];
    const float* w1 = (const float*)d_in[2];
    const float* b1 = (const float*)d_in[3];
    const float* w2 = (const float*)d_in[4];
    const float* b2 = (const float*)d_in[5];
    float* out = (float*)d_out;

    cudaFuncSetAttribute(mma_gemm<Dd, Hh, Dd, Hh, 1, true, Hh>,
                         cudaFuncAttributeMaxDynamicSharedMemorySize, SMEM_BYTES);
    cudaFuncSetAttribute(mma_gemm<Hh, Dd, Hh, Dd, 0, false, Dd>,
                         cudaFuncAttributeMaxDynamicSharedMemorySize, SMEM_BYTES);

    f2h_kernel<<<(Ee * Dd * Hh / 8 + 255) / 256, 256>>>(w1, 1, Ee * Dd * Hh); // + zero g_cnt
    f2h_kernel<<<(Ee * Hh * Dd / 8 + 255) / 256, 256>>>(w2, 2, Ee * Hh * Dd);
    router_kernel<<<Tt / 8, 256>>>(x, rw);   // also emits g_xh

    dim3 g1(Tt / 128, Hh / 128, Ee);
    mma_gemm<Dd, Hh, Dd, Hh, 1, true, Hh><<<g1, 256, SMEM_BYTES>>>(b1);

    dim3 g2(Tt / 128, Dd / 128, Ee);
    mma_gemm<Hh, Dd, Hh, Dd, 0, false, Dd><<<g2, 256, SMEM_BYTES>>>(b2);

    combine_kernel<<<(Tt * Dd / 4) / 256, 256>>>(out);

    int write_loss = (out_size > Tt * Dd) ? 1 : 0;
    loss_kernel<<<1, 256>>>(out, write_loss);
}

// round 17
// speedup vs baseline: 1.4920x; 1.0091x over previous
#include <cuda_runtime.h>
#include <cuda_fp16.h>
#include <math.h>

#define Tt 4096
#define Dd 1024
#define Hh 4096
#define Ee 8
#define Kk 2
#define SK2 4                                   // split-K factor for GEMM2
#define TKD ((size_t)Tt * Kk * Dd)

// ---------------- device scratch ----------------
__device__ int    g_cnt[Ee];
__device__ int    g_slot[Ee * Tt];
__device__ float  g_wt[Tt * Kk];
__device__ float  g_probs[Tt * Ee];
__device__ __half g_xh[(size_t)Tt * Dd];          // x in fp16
__device__ __half g_w1h[(size_t)Ee * Dd * Hh];    // w1 in fp16
__device__ __half g_w2h[(size_t)Ee * Hh * Dd];    // w2 in fp16
__device__ __half g_h[(size_t)Tt * Kk * Hh];      // gelu(x@w1+b1) per slot (fp16)
__device__ float  g_ysp[SK2 * TKD];               // gemm2 split-K partials (fp32)

// ---------------- helpers ----------------
__device__ __forceinline__ unsigned smem_u32(const void* p) {
    unsigned a;
    asm("{ .reg .u64 t; cvta.to.shared.u64 t, %1; cvt.u32.u64 %0, t; }"
        : "=r"(a) : "l"(p));
    return a;
}
__device__ __forceinline__ void cp16(unsigned saddr, const void* g) {
    asm volatile("cp.async.cg.shared.global [%0], [%1], 16;"
                 :: "r"(saddr), "l"(g) : "memory");
}
__device__ __forceinline__ void mma_f16(float* d, const unsigned* a, const unsigned* b) {
    asm volatile(
        "mma.sync.aligned.m16n8k16.row.col.f32.f16.f16.f32 "
        "{%0,%1,%2,%3}, {%4,%5,%6,%7}, {%8,%9}, {%0,%1,%2,%3};"
        : "+f"(d[0]), "+f"(d[1]), "+f"(d[2]), "+f"(d[3])
        : "r"(a[0]), "r"(a[1]), "r"(a[2]), "r"(a[3]), "r"(b[0]), "r"(b[1]));
}
#define LDSM_X4(r, addr) \
    asm volatile("ldmatrix.sync.aligned.m8n8.x4.shared.b16 {%0,%1,%2,%3}, [%4];" \
        : "=r"((r)[0]), "=r"((r)[1]), "=r"((r)[2]), "=r"((r)[3]) : "r"(addr))
#define LDSM_X4_T(r, addr) \
    asm volatile("ldmatrix.sync.aligned.m8n8.x4.trans.shared.b16 {%0,%1,%2,%3}, [%4];" \
        : "=r"((r)[0]), "=r"((r)[1]), "=r"((r)[2]), "=r"((r)[3]) : "r"(addr))

// ---------------- f32 -> f16 weight convert; w1 variant also zeroes g_cnt ----------------
__global__ void f2h_kernel(const float* __restrict__ s, int which, int n) {
    if (which == 1 && blockIdx.x == 0 && threadIdx.x < Ee)
        g_cnt[threadIdx.x] = 0;
    __half* d = (which == 1) ? g_w1h : g_w2h;
    size_t i = ((size_t)blockIdx.x * blockDim.x + threadIdx.x) * 8;
    if (i >= (size_t)n) return;
    float4 v0 = *(const float4*)(s + i);
    float4 v1 = *(const float4*)(s + i + 4);
    __half2 h0 = __floats2half2_rn(v0.x, v0.y);
    __half2 h1 = __floats2half2_rn(v0.z, v0.w);
    __half2 h2 = __floats2half2_rn(v1.x, v1.y);
    __half2 h3 = __floats2half2_rn(v1.z, v1.w);
    uint4 o;
    o.x = *(unsigned*)&h0; o.y = *(unsigned*)&h1;
    o.z = *(unsigned*)&h2; o.w = *(unsigned*)&h3;
    *(uint4*)(d + i) = o;
}

// ---------------- router (+ fused f2h of x): 1 warp per token, float4 loads ----------------
__global__ void router_kernel(const float* __restrict__ x,
                              const float* __restrict__ rw) {
    int tid = threadIdx.x;
    int warp = tid >> 5, lane = tid & 31;
    int t = blockIdx.x * 8 + warp;

    const float4* xr4 = (const float4*)(x + (size_t)t * Dd);
    const float4* rw4 = (const float4*)rw;            // [E][Dd/4]
    uint2* xh2 = (uint2*)(g_xh + (size_t)t * Dd);
    float acc[Ee];
#pragma unroll
    for (int e = 0; e < Ee; e++) acc[e] = 0.f;
#pragma unroll
    for (int d4 = lane, it = 0; it < Dd / 4 / 32; d4 += 32, it++) {
        float4 xv = xr4[d4];
        __half2 h0 = __floats2half2_rn(xv.x, xv.y);
        __half2 h1 = __floats2half2_rn(xv.z, xv.w);
        uint2 u; u.x = *(unsigned*)&h0; u.y = *(unsigned*)&h1;
        xh2[d4] = u;                                   // fused f2h(x)
#pragma unroll
        for (int e = 0; e < Ee; e++) {
            float4 wv = rw4[e * (Dd / 4) + d4];
            acc[e] += xv.x * wv.x + xv.y * wv.y + xv.z * wv.z + xv.w * wv.w;
        }
    }
#pragma unroll
    for (int e = 0; e < Ee; e++)
#pragma unroll
        for (int off = 16; off > 0; off >>= 1)
            acc[e] += __shfl_xor_sync(0xffffffffu, acc[e], off);

    if (lane == 0) {
        float mx = acc[0];
#pragma unroll
        for (int e = 1; e < Ee; e++) mx = fmaxf(mx, acc[e]);
        float pe[Ee], s = 0.f;
#pragma unroll
        for (int e = 0; e < Ee; e++) { pe[e] = __expf(acc[e] - mx); s += pe[e]; }
        float inv = 1.f / s;
#pragma unroll
        for (int e = 0; e < Ee; e++) { pe[e] *= inv; g_probs[t * Ee + e] = pe[e]; }
        int i1 = 0;
#pragma unroll
        for (int e = 1; e < Ee; e++) if (pe[e] > pe[i1]) i1 = e;
        int i2 = (i1 == 0) ? 1 : 0;
#pragma unroll
        for (int e = 0; e < Ee; e++) if (e != i1 && pe[e] > pe[i2]) i2 = e;
        float denom = pe[i1] + pe[i2] + 1e-8f;
        int p1 = atomicAdd(&g_cnt[i1], 1);
        g_slot[i1 * Tt + p1] = t * 2 + 0;
        g_wt[t * 2 + 0] = pe[i1] / denom;
        int p2 = atomicAdd(&g_cnt[i2], 1);
        g_slot[i2 * Tt + p2] = t * 2 + 1;
        g_wt[t * 2 + 1] = pe[i2] / denom;
    }
}

// ---------------- fp16 mma.sync grouped GEMM (proven-best mainloop, unchanged) ----------------
// CTA tile 128x128, K-chunk 64, 8 warps (2x4), warp tile 64x32, 2 CTAs/SM.
// 3-stage cp.async ring, ONE __syncthreads per chunk.
// SPLITK>1 (gemm2): blockIdx.z encodes (expert, split); split sk covers K range
// [sk*K/SPLITK, ...); partials go to g_ysp + sk*TKD; bias added only in sk==0.
#define BK 64
#define A_BUF_B (128 * 144)                   // 18432 B
#define B_BUF_B (64 * 272)                    // 17408 B
#define STAGE_B (A_BUF_B + B_BUF_B)           // 35840 B
#define SM_SLOT_B (3 * STAGE_B)               // 107520
#define SMEM_BYTES (SM_SLOT_B + 512)          // 108032

template<int LDA, int LDW, int KTOT, int NTOT, int SHIFT, bool GELU, int LDO, int SPLITK>
__global__ __launch_bounds__(256, 2)
void mma_gemm(const float* __restrict__ bias) {
    const int zz = blockIdx.z;
    const int e  = (SPLITK == 1) ? zz : (zz & (Ee - 1));
    const int sk = (SPLITK == 1) ? 0 : (zz >> 3);
    const int KLOC = KTOT / SPLITK;
    const int kbase = sk * KLOC;

    const int ne = g_cnt[e];
    const int row0 = blockIdx.x * 128;
    if (row0 >= ne) return;
    const int n0 = blockIdx.y * 128;

    extern __shared__ __align__(16) char smem[];
    int* slot_s = (int*)(smem + SM_SLOT_B);
    const unsigned sb = smem_u32(smem);

    const int tid = threadIdx.x, wid = tid >> 5, lane = tid & 31;
    const int g = lane >> 2, c = lane & 3;

    const __half* A = SHIFT ? g_xh : g_h;
    const __half* W = GELU ? g_w1h : g_w2h;

    if (tid < 128) {
        int r = row0 + tid;
        slot_s[tid] = g_slot[e * Tt + ((r < ne) ? r : (ne - 1))];
    }
    __syncthreads();

    // cp.async mappings: A 2 thr/row (4x16B), B 4 thr/row (4x16B)
    const int arow = tid >> 1, acb = (tid & 1) * 4;
    const __half* aSrc = A + (size_t)(slot_s[arow] >> SHIFT) * LDA + kbase + acb * 8;
    const unsigned aOff = arow * 144 + acb * 16;
    const int brow = tid >> 2, bcb = (tid & 3) * 4;
    const __half* bSrc = W + (size_t)e * KTOT * LDW + (size_t)(kbase + brow) * LDW + n0 + bcb * 8;
    const unsigned bOff = A_BUF_B + brow * 272 + bcb * 16;

    const int NK = KLOC / BK;

    // prologue: chunks 0,1 into stages 0,1
#pragma unroll
    for (int p = 0; p < 2; p++) {
        const unsigned s0 = sb + p * STAGE_B;
        const __half* ap = aSrc + (size_t)p * BK;
        const __half* bp = bSrc + (size_t)p * BK * LDW;
#pragma unroll
        for (int q = 0; q < 4; q++) cp16(s0 + aOff + q * 16, ap + q * 8);
#pragma unroll
        for (int q = 0; q < 4; q++) cp16(s0 + bOff + q * 16, bp + q * 8);
        asm volatile("cp.async.commit_group;" ::: "memory");
    }

    const int wm = (wid >> 2) * 64;
    const int wn = (wid & 3) * 32;

    // ldmatrix lane base offsets (within a stage)
    const unsigned aLd = (wm + (lane & 15)) * 144 + (lane >> 4) * 16;
    const unsigned bLd = A_BUF_B + (lane & 15) * 272 + wn * 2 + (lane >> 4) * 16;

    float acc[4][4][4];
#pragma unroll
    for (int mf = 0; mf < 4; mf++)
#pragma unroll
        for (int nf = 0; nf < 4; nf++)
#pragma unroll
            for (int v = 0; v < 4; v++) acc[mf][nf][v] = 0.f;

    int cs = 0;  // compute stage
    for (int i = 0; i < NK; i++) {
        if (i + 1 < NK) asm volatile("cp.async.wait_group 1;" ::: "memory");
        else            asm volatile("cp.async.wait_group 0;" ::: "memory");
        __syncthreads();

        // issue chunk i+2 into stage (cs+2)%3 — freed: all warps passed compute(i-1)
        if (i + 2 < NK) {
            const int ts = (cs == 0) ? 2 : cs - 1;
            const unsigned s0 = sb + ts * STAGE_B;
            const __half* ap = aSrc + (size_t)(i + 2) * BK;
            const __half* bp = bSrc + (size_t)(i + 2) * BK * LDW;
#pragma unroll
            for (int q = 0; q < 4; q++) cp16(s0 + aOff + q * 16, ap + q * 8);
#pragma unroll
            for (int q = 0; q < 4; q++) cp16(s0 + bOff + q * 16, bp + q * 8);
            asm volatile("cp.async.commit_group;" ::: "memory");
        }

        const unsigned ab = sb + cs * STAGE_B + aLd;
        const unsigned bb0 = sb + cs * STAGE_B + bLd;
#pragma unroll
        for (int ks = 0; ks < 4; ks++) {
            unsigned a[4][4], bb[2][4];
#pragma unroll
            for (int mf = 0; mf < 4; mf++)
                LDSM_X4(a[mf], ab + mf * (16 * 144) + ks * 32);
            LDSM_X4_T(bb[0], bb0 + ks * (16 * 272));
            LDSM_X4_T(bb[1], bb0 + ks * (16 * 272) + 32);
#pragma unroll
            for (int mf = 0; mf < 4; mf++)
#pragma unroll
                for (int nf = 0; nf < 4; nf++)
                    mma_f16(acc[mf][nf], a[mf], &bb[nf >> 1][(nf & 1) * 2]);
        }
        cs = (cs == 2) ? 0 : cs + 1;
    }

    // ---------------- epilogue ----------------
    float* OUTF = g_ysp + (size_t)sk * TKD;   // used when !GELU
#pragma unroll
    for (int mf = 0; mf < 4; mf++) {
#pragma unroll
        for (int half_i = 0; half_i < 2; half_i++) {
            const int r = wm + mf * 16 + g + half_i * 8;
            if (row0 + r >= ne) continue;
            const int s = slot_s[r];
#pragma unroll
            for (int nf = 0; nf < 4; nf++) {
                const int col = wn + nf * 8 + c * 2;
                const float b0 = (sk == 0) ? bias[e * NTOT + n0 + col]     : 0.f;
                const float b1 = (sk == 0) ? bias[e * NTOT + n0 + col + 1] : 0.f;
                float v0 = acc[mf][nf][half_i * 2 + 0] + b0;
                float v1 = acc[mf][nf][half_i * 2 + 1] + b1;
                if (GELU) {
                    v0 = 0.5f * v0 * (1.f + erff(v0 * 0.70710678118654752440f));
                    v1 = 0.5f * v1 * (1.f + erff(v1 * 0.70710678118654752440f));
                    __half2 h2 = __floats2half2_rn(v0, v1);
                    *(__half2*)(g_h + (size_t)s * LDO + n0 + col) = h2;
                } else {
                    float2 o; o.x = v0; o.y = v1;
                    *(float2*)(OUTF + (size_t)s * LDO + n0 + col) = o;
                }
            }
        }
    }
}

// ---------------- combine (+ fused load-balancing loss in the extra block) ----------------
__global__ void combine_kernel(float* __restrict__ out, int write_loss) {
    if (blockIdx.x == (Tt * Dd / 4) / 256) {
        // loss block
        __shared__ float sred[256 * Ee];
        int tid = threadIdx.x;
        float l[Ee];
#pragma unroll
        for (int e = 0; e < Ee; e++) l[e] = 0.f;
        for (int t = tid; t < Tt; t += 256)
#pragma unroll
            for (int e = 0; e < Ee; e++) l[e] += g_probs[t * Ee + e];
#pragma unroll
        for (int e = 0; e < Ee; e++) sred[tid * Ee + e] = l[e];
        __syncthreads();
        for (int s = 128; s > 0; s >>= 1) {
            if (tid < s)
#pragma unroll
                for (int e = 0; e < Ee; e++)
                    sred[tid * Ee + e] += sred[(tid + s) * Ee + e];
            __syncthreads();
        }
        if (tid == 0 && write_loss) {
            float loss = 0.f;
            for (int e = 0; e < Ee; e++) {
                float mean_p = sred[e] / (float)Tt;
                float frac = (float)g_cnt[e] / (float)(Tt * Kk);
                loss += mean_p * frac;
            }
            out[(size_t)Tt * Dd] = loss * (float)Ee;
        }
        return;
    }

    int i = blockIdx.x * blockDim.x + threadIdx.x;
    int t = i >> 8;
    int d4 = i & 255;
    float w0 = g_wt[2 * t], w1 = g_wt[2 * t + 1];
    const float4* y = (const float4*)g_ysp;
    size_t i0 = (size_t)(2 * t) * 256 + d4;
    size_t i1 = (size_t)(2 * t + 1) * 256 + d4;
    const size_t SP = TKD / 4;          // float4 stride between splits

    float4 a = y[i0];
    float4 b = y[i1];
#pragma unroll
    for (int s = 1; s < SK2; s++) {
        float4 as = y[s * SP + i0];
        float4 bs = y[s * SP + i1];
        a.x += as.x; a.y += as.y; a.z += as.z; a.w += as.w;
        b.x += bs.x; b.y += bs.y; b.z += bs.z; b.w += bs.w;
    }
    float4 o;
    o.x = w0 * a.x + w1 * b.x;
    o.y = w0 * a.y + w1 * b.y;
    o.z = w0 * a.z + w1 * b.z;
    o.w = w0 * a.w + w1 * b.w;
    ((float4*)out)[i] = o;
}

// ---------------- launch ----------------
// My 4th launch = process launch #6 (2 harness extras) => ncu -s 5 profiles gemm1.
extern "C" void kernel_launch(void* const* d_in, const int* in_sizes, int n_in,
                              void* d_out, int out_size) {
    const float* x  = (const float*)d_in[0];
    const float* rw = (const float*)d_in[1];
    const float* w1 = (const float*)d_in[2];
    const float* b1 = (const float*)d_in[3];
    const float* w2 = (const float*)d_in[4];
    const float* b2 = (const float*)d_in[5];
    float* out = (float*)d_out;

    cudaFuncSetAttribute(mma_gemm<Dd, Hh, Dd, Hh, 1, true, Hh, 1>,
                         cudaFuncAttributeMaxDynamicSharedMemorySize, SMEM_BYTES);
    cudaFuncSetAttribute(mma_gemm<Hh, Dd, Hh, Dd, 0, false, Dd, SK2>,
                         cudaFuncAttributeMaxDynamicSharedMemorySize, SMEM_BYTES);

    f2h_kernel<<<(Ee * Dd * Hh / 8 + 255) / 256, 256>>>(w1, 1, Ee * Dd * Hh); // + zero g_cnt
    f2h_kernel<<<(Ee * Hh * Dd / 8 + 255) / 256, 256>>>(w2, 2, Ee * Hh * Dd);
    router_kernel<<<Tt / 8, 256>>>(x, rw);   // also emits g_xh

    dim3 g1(Tt / 128, Hh / 128, Ee);
    mma_gemm<Dd, Hh, Dd, Hh, 1, true, Hh, 1><<<g1, 256, SMEM_BYTES>>>(b1);

    dim3 g2(Tt / 128, Dd / 128, Ee * SK2);   // split-K=4: 6.92 waves, 98.8% util
    mma_gemm<Hh, Dd, Hh, Dd, 0, false, Dd, SK2><<<g2, 256, SMEM_BYTES>>>(b2);

    int write_loss = (out_size > Tt * Dd) ? 1 : 0;
    combine_kernel<<<(Tt * Dd / 4) / 256 + 1, 256>>>(out, write_loss);
}